// round 1
// baseline (speedup 1.0000x reference)
#include <cuda_runtime.h>
#include <cstdint>

// Problem constants
#define Bb   2
#define Nn   2048
#define Cc   512
#define Hh   8
#define HD   64
#define BH   16           // B*H
#define KTOP 1024
#define SCALEF 0.125f

// ---------------- scratch (device globals; no allocation allowed) ----------
__device__ float g_Qh[BH * Nn * HD];                 // [B,H,N,HD]  8MB
__device__ float g_Kh[BH * Nn * HD];
__device__ float g_Vh[BH * Nn * HD];
__device__ float g_attn[(size_t)BH * Nn * Nn];       // 256MB
__device__ float g_attnT[(size_t)BH * Nn * Nn];      // 256MB
__device__ float g_rth[BH * Nn];                     // row thresholds
__device__ float g_cth[BH * Nn];                     // col thresholds
__device__ float g_rmax[BH * Nn];                    // row maxima
__device__ float g_O[BH * Nn * HD];                  // attention output pre-proj

// ---------------------------------------------------------------------------
// Kernel 1: projections  out = X @ W^T  scattered to [B,H,N,HD]
// grid (Cc/64, M/64), block 256, 64x64 tile, 4x4 per thread, BK=32
// ---------------------------------------------------------------------------
__global__ void proj_kernel(const float* __restrict__ X,
                            const float* __restrict__ W, int which) {
    __shared__ float As[64][33];
    __shared__ float Ws[64][33];
    int tid = threadIdx.x;
    int tx = tid & 15, ty = tid >> 4;
    int m0 = blockIdx.y * 64, n0 = blockIdx.x * 64;
    float acc[4][4] = {};
    for (int k0 = 0; k0 < Cc; k0 += 32) {
        for (int l = tid; l < 64 * 32; l += 256) {
            int r = l >> 5, c = l & 31;
            As[r][c] = X[(size_t)(m0 + r) * Cc + k0 + c];
            Ws[r][c] = W[(size_t)(n0 + r) * Cc + k0 + c];
        }
        __syncthreads();
#pragma unroll
        for (int kk = 0; kk < 32; kk++) {
            float a[4], b[4];
#pragma unroll
            for (int i = 0; i < 4; i++) a[i] = As[ty * 4 + i][kk];
#pragma unroll
            for (int j = 0; j < 4; j++) b[j] = Ws[tx * 4 + j][kk];
#pragma unroll
            for (int i = 0; i < 4; i++)
#pragma unroll
                for (int j = 0; j < 4; j++) acc[i][j] += a[i] * b[j];
        }
        __syncthreads();
    }
    float* out = (which == 0) ? g_Qh : ((which == 1) ? g_Kh : g_Vh);
#pragma unroll
    for (int i = 0; i < 4; i++) {
        int m = m0 + ty * 4 + i;
        int bb = m >> 11, nl = m & (Nn - 1);
#pragma unroll
        for (int j = 0; j < 4; j++) {
            int n = n0 + tx * 4 + j;
            int h = n >> 6, d = n & 63;
            out[(((size_t)(bb * Hh + h)) * Nn + nl) * HD + d] = acc[i][j];
        }
    }
}

// ---------------------------------------------------------------------------
// Kernel 2: attn = scale * Q K^T per (b,h), also writes transposed copy.
// grid (N/64, N/64, BH), block 256
// ---------------------------------------------------------------------------
__global__ void qk_kernel() {
    __shared__ float Qs[64][65];
    __shared__ float Ks[64][65];
    int tid = threadIdx.x;
    int tx = tid & 15, ty = tid >> 4;
    int bh = blockIdx.z;
    int i0 = blockIdx.y * 64, j0 = blockIdx.x * 64;
    const float* Q = g_Qh + (size_t)bh * Nn * HD;
    const float* K = g_Kh + (size_t)bh * Nn * HD;
    for (int l = tid; l < 64 * 64; l += 256) {
        int r = l >> 6, c = l & 63;
        Qs[r][c] = Q[(size_t)(i0 + r) * HD + c];
        Ks[r][c] = K[(size_t)(j0 + r) * HD + c];
    }
    __syncthreads();
    float acc[4][4] = {};
#pragma unroll 16
    for (int kk = 0; kk < 64; kk++) {
        float a[4], b[4];
#pragma unroll
        for (int i = 0; i < 4; i++) a[i] = Qs[ty * 4 + i][kk];
#pragma unroll
        for (int j = 0; j < 4; j++) b[j] = Ks[tx * 4 + j][kk];
#pragma unroll
        for (int i = 0; i < 4; i++)
#pragma unroll
            for (int j = 0; j < 4; j++) acc[i][j] += a[i] * b[j];
    }
    __syncthreads();   // done reading Qs/Ks
    // scale + direct store (coalesced float4)
    float* attn = g_attn + ((size_t)bh * Nn + i0) * Nn + j0;
#pragma unroll
    for (int i = 0; i < 4; i++) {
#pragma unroll
        for (int j = 0; j < 4; j++) acc[i][j] *= SCALEF;
        float4 v = make_float4(acc[i][0], acc[i][1], acc[i][2], acc[i][3]);
        *(float4*)&attn[(size_t)(ty * 4 + i) * Nn + tx * 4] = v;
        // stage for transpose
#pragma unroll
        for (int j = 0; j < 4; j++) Qs[ty * 4 + i][tx * 4 + j] = acc[i][j];
    }
    __syncthreads();
    float* attnT = g_attnT + ((size_t)bh * Nn + j0) * Nn + i0;
    for (int l = tid; l < 64 * 64; l += 256) {
        int jl = l >> 6, il = l & 63;
        attnT[(size_t)jl * Nn + il] = Qs[il][jl];   // stride-65 read: conflict-free
    }
}

// ---------------------------------------------------------------------------
// Kernel 3: per-row exact K_TOP-th-largest via MSB-first 8-bit radix select.
// grid (BH*N, 2): y==0 -> rows of attn (also row max), y==1 -> rows of attnT.
// block 256.
// ---------------------------------------------------------------------------
__global__ void select_kernel() {
    __shared__ unsigned sd[Nn];
    __shared__ unsigned hist[256];
    __shared__ unsigned scanbuf[256];
    __shared__ unsigned s_sel, s_sub, s_max;
    int tid = threadIdx.x;
    size_t row = blockIdx.x;
    int dir = blockIdx.y;
    const float* src = (dir ? g_attnT : g_attn) + row * Nn;
    if (tid == 0) s_max = 0u;
    __syncthreads();
    unsigned lmax = 0u;
    for (int e = tid; e < Nn; e += 256) {
        unsigned b = __float_as_uint(src[e]);
        unsigned u = (b & 0x80000000u) ? ~b : (b | 0x80000000u);  // order-preserving
        sd[e] = u;
        lmax = lmax > u ? lmax : u;
    }
    atomicMax(&s_max, lmax);

    unsigned prefix = 0u;
    int krem = KTOP;
    for (int shift = 24; shift >= 0; shift -= 8) {
        hist[tid] = 0u;
        __syncthreads();                       // also covers initial sd visibility
        unsigned hi_mask = (shift == 24) ? 0u : (0xFFFFFFFFu << (shift + 8));
        for (int e = tid; e < Nn; e += 256) {
            unsigned u = sd[e];
            if ((u & hi_mask) == prefix) atomicAdd(&hist[(u >> shift) & 255u], 1u);
        }
        __syncthreads();
        // suffix sums S[t] = sum_{b>=t} hist[b] via reversed Hillis-Steele scan
        unsigned v = hist[255 - tid];
        for (int off = 1; off < 256; off <<= 1) {
            scanbuf[tid] = v;
            __syncthreads();
            if (tid >= off) v += scanbuf[tid - off];
            __syncthreads();
        }
        scanbuf[255 - tid] = v;
        __syncthreads();
        unsigned St  = scanbuf[tid];
        unsigned St1 = (tid == 255) ? 0u : scanbuf[tid + 1];
        if ((int)St >= krem && (int)St1 < krem) { s_sel = (unsigned)tid; s_sub = St1; }
        __syncthreads();
        prefix |= (s_sel << shift);
        krem -= (int)s_sub;
        __syncthreads();
    }
    if (tid == 0) {
        unsigned u = prefix;
        unsigned b = (u & 0x80000000u) ? (u ^ 0x80000000u) : ~u;
        float thr = __uint_as_float(b);
        if (dir) {
            g_cth[row] = thr;
        } else {
            g_rth[row] = thr;
            unsigned um = s_max;
            unsigned bm = (um & 0x80000000u) ? (um ^ 0x80000000u) : ~um;
            g_rmax[row] = __uint_as_float(bm);
        }
    }
}

// ---------------------------------------------------------------------------
// Kernel 4: fused masked softmax + P@V.  grid (N/64, BH), block 256.
// Streams attn in 64x32 chunks; p computed in-place; denominator kept
// per-thread (4 threads own one row's loads) -> single atomicAdd at end.
// ---------------------------------------------------------------------------
__global__ void spv_kernel() {
    __shared__ float Ps[64][33];
    __shared__ float Vs[32][65];
    __shared__ float s_rth[64], s_m[64], s_cth[32], s_den[64];
    int tid = threadIdx.x;
    int tx = tid & 15, ty = tid >> 4;
    int bh = blockIdx.y;
    int i0 = blockIdx.x * 64;
    const float* V = g_Vh + (size_t)bh * Nn * HD;
    const float* A = g_attn + ((size_t)bh * Nn + i0) * Nn;
    if (tid < 64) {
        s_rth[tid] = g_rth[bh * Nn + i0 + tid];
        s_m[tid]   = g_rmax[bh * Nn + i0 + tid];
        s_den[tid] = 0.f;
    }
    __syncthreads();
    int rp = tid >> 2;             // row this thread loads/transforms
    int cbase = (tid & 3) * 8;     // its 8 columns within the 32-chunk
    float rthr = s_rth[rp];
    float mr   = s_m[rp];
    float acc[4][4] = {};
    float dloc = 0.f;

    for (int j0 = 0; j0 < Nn; j0 += 32) {
        __syncthreads();           // previous chunk's compute finished
        if (tid < 32) s_cth[tid] = g_cth[bh * Nn + j0 + tid];
        for (int l = tid; l < 32 * 64; l += 256) {
            int jl = l >> 6, d = l & 63;
            Vs[jl][d] = V[(size_t)(j0 + jl) * HD + d];
        }
#pragma unroll
        for (int u = 0; u < 8; u++)
            Ps[rp][cbase + u] = A[(size_t)rp * Nn + j0 + cbase + u];
        __syncthreads();           // cth + raw loads visible
#pragma unroll
        for (int u = 0; u < 8; u++) {
            float a = Ps[rp][cbase + u];
            float thr = fminf(rthr, s_cth[cbase + u]);
            float p = (a >= thr) ? __expf(a - mr) : 0.f;
            Ps[rp][cbase + u] = p;
            dloc += p;
        }
        __syncthreads();           // transformed P visible
#pragma unroll
        for (int jj = 0; jj < 32; jj++) {
            float a[4], b[4];
#pragma unroll
            for (int i = 0; i < 4; i++) a[i] = Ps[ty * 4 + i][jj];
#pragma unroll
            for (int j = 0; j < 4; j++) b[j] = Vs[jj][tx * 4 + j];
#pragma unroll
            for (int i = 0; i < 4; i++)
#pragma unroll
                for (int j = 0; j < 4; j++) acc[i][j] += a[i] * b[j];
        }
    }
    atomicAdd(&s_den[rp], dloc);
    __syncthreads();
#pragma unroll
    for (int i = 0; i < 4; i++) {
        int il = ty * 4 + i;
        float inv = 1.f / s_den[il];
#pragma unroll
        for (int j = 0; j < 4; j++)
            g_O[((size_t)bh * Nn + i0 + il) * HD + tx * 4 + j] = acc[i][j] * inv;
    }
}

// ---------------------------------------------------------------------------
// Kernel 5: output projection  out = concat_heads(O) @ Wp^T + bp
// grid (Cc/64, M/64), block 256
// ---------------------------------------------------------------------------
__global__ void outproj_kernel(const float* __restrict__ Wp,
                               const float* __restrict__ bp,
                               float* __restrict__ out) {
    __shared__ float As[64][33];
    __shared__ float Ws[64][33];
    int tid = threadIdx.x;
    int tx = tid & 15, ty = tid >> 4;
    int m0 = blockIdx.y * 64, n0 = blockIdx.x * 64;
    float acc[4][4] = {};
    for (int k0 = 0; k0 < Cc; k0 += 32) {
        for (int l = tid; l < 64 * 32; l += 256) {
            int r = l >> 5, c = l & 31;
            int m = m0 + r;
            int bb = m >> 11, nl = m & (Nn - 1);
            int k = k0 + c;
            int h = k >> 6, d = k & 63;
            As[r][c] = g_O[(((size_t)(bb * Hh + h)) * Nn + nl) * HD + d];
            Ws[r][c] = Wp[(size_t)(n0 + r) * Cc + k];
        }
        __syncthreads();
#pragma unroll
        for (int kk = 0; kk < 32; kk++) {
            float a[4], b[4];
#pragma unroll
            for (int i = 0; i < 4; i++) a[i] = As[ty * 4 + i][kk];
#pragma unroll
            for (int j = 0; j < 4; j++) b[j] = Ws[tx * 4 + j][kk];
#pragma unroll
            for (int i = 0; i < 4; i++)
#pragma unroll
                for (int j = 0; j < 4; j++) acc[i][j] += a[i] * b[j];
        }
        __syncthreads();
    }
#pragma unroll
    for (int i = 0; i < 4; i++) {
        int m = m0 + ty * 4 + i;
#pragma unroll
        for (int j = 0; j < 4; j++) {
            int n = n0 + tx * 4 + j;
            out[(size_t)m * Cc + n] = acc[i][j] + bp[n];
        }
    }
}

// ---------------------------------------------------------------------------
extern "C" void kernel_launch(void* const* d_in, const int* in_sizes, int n_in,
                              void* d_out, int out_size) {
    (void)in_sizes; (void)n_in; (void)out_size;
    const float* q   = (const float*)d_in[0];
    const float* k_v = (const float*)d_in[1];
    const float* Wq  = (const float*)d_in[2];
    const float* Wk  = (const float*)d_in[3];
    const float* Wv  = (const float*)d_in[4];
    const float* Wp  = (const float*)d_in[5];
    const float* bp  = (const float*)d_in[6];
    float* out = (float*)d_out;

    dim3 blk(256);
    dim3 gproj(Cc / 64, (Bb * Nn) / 64);          // (8, 64)
    proj_kernel<<<gproj, blk>>>(q,   Wq, 0);
    proj_kernel<<<gproj, blk>>>(k_v, Wk, 1);
    proj_kernel<<<gproj, blk>>>(k_v, Wv, 2);

    dim3 gqk(Nn / 64, Nn / 64, BH);               // (32, 32, 16)
    qk_kernel<<<gqk, blk>>>();

    dim3 gsel(BH * Nn, 2);                        // 65536 selects
    select_kernel<<<gsel, blk>>>();

    dim3 gspv(Nn / 64, BH);                       // (32, 16)
    spv_kernel<<<gspv, blk>>>();

    dim3 gout(Cc / 64, (Bb * Nn) / 64);
    outproj_kernel<<<gout, blk>>>(Wp, bp, out);
}

// round 2
// speedup vs baseline: 1.3027x; 1.3027x over previous
#include <cuda_runtime.h>
#include <cstdint>

#define Bb   2
#define Nn   2048
#define Cc   512
#define Hh   8
#define HD   64
#define BH   16
#define KTOP 1024
#define SCALEF 0.125f

// ---------------- scratch ----------------
__device__ float g_Qh[BH * Nn * HD];
__device__ float g_Kh[BH * Nn * HD];
__device__ float g_Vh[BH * Nn * HD];
__device__ float g_attn[(size_t)BH * Nn * Nn];
__device__ float g_attnT[(size_t)BH * Nn * Nn];
__device__ float g_rth[BH * Nn];
__device__ float g_cth[BH * Nn];
__device__ float g_rmax[BH * Nn];
__device__ float g_O[BH * Nn * HD];

// ---------------------------------------------------------------------------
// Kernel 1: projections  out = X @ W^T  scattered to [B,H,N,HD]
// tile 128x64, 128 threads, 8x8 per thread, BK=32
// ---------------------------------------------------------------------------
__global__ __launch_bounds__(128) void proj_kernel(const float* __restrict__ X,
                                                   const float* __restrict__ W,
                                                   int which) {
    __shared__ float As[128][33];
    __shared__ float Bs[64][33];
    int tid = threadIdx.x;
    int tx = tid & 7, ty = tid >> 3;
    int m0 = blockIdx.y * 128, n0 = blockIdx.x * 64;
    float acc[8][8] = {};
    for (int k0 = 0; k0 < Cc; k0 += 32) {
#pragma unroll
        for (int l = tid; l < 1024; l += 128) {          // 128x32 floats as float4
            int m = l >> 3, c = (l & 7) * 4;
            float4 v = *(const float4*)&X[(size_t)(m0 + m) * Cc + k0 + c];
            As[m][c] = v.x; As[m][c + 1] = v.y; As[m][c + 2] = v.z; As[m][c + 3] = v.w;
        }
#pragma unroll
        for (int l = tid; l < 512; l += 128) {           // 64x32 floats
            int n = l >> 3, c = (l & 7) * 4;
            float4 v = *(const float4*)&W[(size_t)(n0 + n) * Cc + k0 + c];
            Bs[n][c] = v.x; Bs[n][c + 1] = v.y; Bs[n][c + 2] = v.z; Bs[n][c + 3] = v.w;
        }
        __syncthreads();
#pragma unroll
        for (int kk = 0; kk < 32; kk++) {
            float a[8], b[8];
#pragma unroll
            for (int i = 0; i < 8; i++) a[i] = As[8 * ty + i][kk];
#pragma unroll
            for (int j = 0; j < 8; j++) b[j] = Bs[8 * tx + j][kk];
#pragma unroll
            for (int i = 0; i < 8; i++)
#pragma unroll
                for (int j = 0; j < 8; j++) acc[i][j] += a[i] * b[j];
        }
        __syncthreads();
    }
    float* out = (which == 0) ? g_Qh : ((which == 1) ? g_Kh : g_Vh);
#pragma unroll
    for (int i = 0; i < 8; i++) {
        int m = m0 + 8 * ty + i;
        int bb = m >> 11, nl = m & (Nn - 1);
#pragma unroll
        for (int j = 0; j < 8; j++) {
            int n = n0 + 8 * tx + j;
            int h = n >> 6, d = n & 63;
            out[(((size_t)(bb * Hh + h)) * Nn + nl) * HD + d] = acc[i][j];
        }
    }
}

// ---------------------------------------------------------------------------
// Kernel 2: attn = scale * Q K^T, also transposed copy.
// tile 128(i) x 64(j), 128 threads, 8x8 per thread, BK=32 (K=64 total)
// ---------------------------------------------------------------------------
__global__ __launch_bounds__(128) void qk_kernel() {
    __shared__ float sm[64 * 129];   // reused: Qs[128][33]+Ks[64][33] then Ts[64][129]
    float (*Qs)[33] = (float(*)[33])sm;
    float (*Ks)[33] = (float(*)[33])(sm + 128 * 33);
    float (*Ts)[129] = (float(*)[129])sm;
    int tid = threadIdx.x;
    int tx = tid & 7, ty = tid >> 3;
    int bh = blockIdx.z;
    int i0 = blockIdx.y * 128, j0 = blockIdx.x * 64;
    const float* Q = g_Qh + (size_t)bh * Nn * HD;
    const float* K = g_Kh + (size_t)bh * Nn * HD;
    float acc[8][8] = {};
#pragma unroll
    for (int k0 = 0; k0 < HD; k0 += 32) {
#pragma unroll
        for (int l = tid; l < 1024; l += 128) {
            int m = l >> 3, c = (l & 7) * 4;
            float4 v = *(const float4*)&Q[(size_t)(i0 + m) * HD + k0 + c];
            Qs[m][c] = v.x; Qs[m][c + 1] = v.y; Qs[m][c + 2] = v.z; Qs[m][c + 3] = v.w;
        }
#pragma unroll
        for (int l = tid; l < 512; l += 128) {
            int n = l >> 3, c = (l & 7) * 4;
            float4 v = *(const float4*)&K[(size_t)(j0 + n) * HD + k0 + c];
            Ks[n][c] = v.x; Ks[n][c + 1] = v.y; Ks[n][c + 2] = v.z; Ks[n][c + 3] = v.w;
        }
        __syncthreads();
#pragma unroll
        for (int kk = 0; kk < 32; kk++) {
            float a[8], b[8];
#pragma unroll
            for (int i = 0; i < 8; i++) a[i] = Qs[8 * ty + i][kk];
#pragma unroll
            for (int j = 0; j < 8; j++) b[j] = Ks[8 * tx + j][kk];
#pragma unroll
            for (int i = 0; i < 8; i++)
#pragma unroll
                for (int j = 0; j < 8; j++) acc[i][j] += a[i] * b[j];
        }
        __syncthreads();
    }
    // scale, write attn directly, stage transpose
    float* attn = g_attn + ((size_t)bh * Nn + i0) * Nn + j0;
#pragma unroll
    for (int i = 0; i < 8; i++) {
#pragma unroll
        for (int j = 0; j < 8; j++) acc[i][j] *= SCALEF;
        float4 v0 = make_float4(acc[i][0], acc[i][1], acc[i][2], acc[i][3]);
        float4 v1 = make_float4(acc[i][4], acc[i][5], acc[i][6], acc[i][7]);
        *(float4*)&attn[(size_t)(8 * ty + i) * Nn + 8 * tx] = v0;
        *(float4*)&attn[(size_t)(8 * ty + i) * Nn + 8 * tx + 4] = v1;
#pragma unroll
        for (int j = 0; j < 8; j++) Ts[8 * tx + j][8 * ty + i] = acc[i][j];
    }
    __syncthreads();
    float* attnT = g_attnT + ((size_t)bh * Nn + j0) * Nn + i0;
#pragma unroll 4
    for (int jl = 0; jl < 64; jl++)
        attnT[(size_t)jl * Nn + tid] = Ts[jl][tid];
}

// ---------------------------------------------------------------------------
// Kernel 3: exact K_TOP-th largest per row via MSB-first 8-bit radix select.
// Elements live in registers (8/thread). 4 sub-histograms, warp suffix-scan.
// grid (BH*N, 2), block 256.
// ---------------------------------------------------------------------------
__global__ __launch_bounds__(256) void select_kernel() {
    __shared__ unsigned hist[4][256];
    __shared__ unsigned S[257];
    __shared__ unsigned s_sel, s_maxu;
    int tid = threadIdx.x;
    size_t row = blockIdx.x;
    int dir = blockIdx.y;
    const float* src = (dir ? g_attnT : g_attn) + row * Nn;

    unsigned u[8], lmax = 0u;
#pragma unroll
    for (int r = 0; r < 8; r++) {
        unsigned b = __float_as_uint(src[tid + 256 * r]);
        u[r] = b ^ ((unsigned)((int)b >> 31) | 0x80000000u);
        lmax = lmax > u[r] ? lmax : u[r];
    }
    if (tid == 0) s_maxu = 0u;

    unsigned prefix = 0u;
    int krem = KTOP;
    int hb = tid >> 6;
#pragma unroll
    for (int pass = 0; pass < 4; pass++) {
        int shift = 24 - 8 * pass;
        hist[0][tid] = 0u; hist[1][tid] = 0u; hist[2][tid] = 0u; hist[3][tid] = 0u;
        __syncthreads();
        if (pass == 0) atomicMax(&s_maxu, lmax);
        unsigned himask = (pass == 0) ? 0u : (0xFFFFFFFFu << (shift + 8));
#pragma unroll
        for (int r = 0; r < 8; r++)
            if ((u[r] & himask) == prefix)
                atomicAdd(&hist[hb][(u[r] >> shift) & 255u], 1u);
        __syncthreads();
        unsigned h = hist[0][tid] + hist[1][tid] + hist[2][tid] + hist[3][tid];
        hist[0][tid] = h;
        __syncthreads();
        if (tid < 32) {
            int base = tid * 8;
            unsigned c[8], loc[8];
#pragma unroll
            for (int j = 0; j < 8; j++) c[j] = hist[0][base + j];
            loc[7] = c[7];
#pragma unroll
            for (int j = 6; j >= 0; j--) loc[j] = c[j] + loc[j + 1];
            unsigned T = loc[0], incl = T;
#pragma unroll
            for (int off = 1; off < 32; off <<= 1) {
                unsigned v = __shfl_down_sync(0xFFFFFFFFu, incl, off);
                if (tid + off < 32) incl += v;
            }
            unsigned excl = incl - T;
#pragma unroll
            for (int j = 0; j < 8; j++) S[base + j] = excl + loc[j];
            if (tid == 0) S[256] = 0u;
        }
        __syncthreads();
        unsigned St = S[tid], St1 = S[tid + 1];
        if ((int)St >= krem && (int)St1 < krem) s_sel = (unsigned)tid;
        __syncthreads();
        unsigned sel = s_sel;
        krem -= (int)S[sel + 1];
        prefix |= sel << shift;
        __syncthreads();
    }
    if (tid == 0) {
        unsigned b = (prefix & 0x80000000u) ? (prefix ^ 0x80000000u) : ~prefix;
        float thr = __uint_as_float(b);
        if (dir) {
            g_cth[row] = thr;
        } else {
            g_rth[row] = thr;
            unsigned um = s_maxu;
            unsigned bm = (um & 0x80000000u) ? (um ^ 0x80000000u) : ~um;
            g_rmax[row] = __uint_as_float(bm);
        }
    }
}

// ---------------------------------------------------------------------------
// Kernel 4: fused masked softmax + P@V.  tile 128 rows x 64 HD, 128 threads,
// 8x8 per thread, K chunks of 32.  grid (N/128, BH).
// ---------------------------------------------------------------------------
__global__ __launch_bounds__(128) void spv_kernel() {
    __shared__ float Ps[128][33];
    __shared__ float Vs[32][68];
    __shared__ float s_rth[128], s_mx[128], s_cth[32], s_den[128];
    int tid = threadIdx.x;
    int tx = tid & 7, ty = tid >> 3;
    int bh = blockIdx.y;
    int i0 = blockIdx.x * 128;
    const float* V = g_Vh + (size_t)bh * Nn * HD;
    const float* A = g_attn + ((size_t)bh * Nn + i0) * Nn;
    s_rth[tid] = g_rth[bh * Nn + i0 + tid];
    s_mx[tid]  = g_rmax[bh * Nn + i0 + tid];
    s_den[tid] = 0.f;
    __syncthreads();
    float rthr[8], mr[8], dloc[8];
#pragma unroll
    for (int i = 0; i < 8; i++) {
        rthr[i] = s_rth[8 * ty + i];
        mr[i]   = s_mx[8 * ty + i];
        dloc[i] = 0.f;
    }
    float acc[8][8] = {};

    for (int j0 = 0; j0 < Nn; j0 += 32) {
        // prefetch raw attn into regs (no smem dependency)
        float4 araw[8];
#pragma unroll
        for (int i = 0; i < 8; i++)
            araw[i] = *(const float4*)&A[(size_t)(8 * ty + i) * Nn + j0 + 4 * tx];
        __syncthreads();               // prev chunk MMA finished
        if (tid < 32) s_cth[tid] = g_cth[bh * Nn + j0 + tid];
#pragma unroll
        for (int l = tid; l < 512; l += 128) {   // V chunk 32x64
            int jl = l >> 4, d = (l & 15) * 4;
            *(float4*)&Vs[jl][d] = *(const float4*)&V[(size_t)(j0 + jl) * HD + d];
        }
        __syncthreads();               // cth + Vs visible
#pragma unroll
        for (int i = 0; i < 8; i++) {
            float av[4] = {araw[i].x, araw[i].y, araw[i].z, araw[i].w};
#pragma unroll
            for (int uu = 0; uu < 4; uu++) {
                float a = av[uu];
                float thr = fminf(rthr[i], s_cth[4 * tx + uu]);
                float p = (a >= thr) ? __expf(a - mr[i]) : 0.f;
                dloc[i] += p;
                Ps[8 * ty + i][4 * tx + uu] = p;
            }
        }
        __syncthreads();               // Ps complete
#pragma unroll
        for (int kk = 0; kk < 32; kk++) {
            float a[8], b[8];
#pragma unroll
            for (int i = 0; i < 8; i++) a[i] = Ps[8 * ty + i][kk];
            float4 b0 = *(const float4*)&Vs[kk][8 * tx];
            float4 b1 = *(const float4*)&Vs[kk][8 * tx + 4];
            b[0] = b0.x; b[1] = b0.y; b[2] = b0.z; b[3] = b0.w;
            b[4] = b1.x; b[5] = b1.y; b[6] = b1.z; b[7] = b1.w;
#pragma unroll
            for (int i = 0; i < 8; i++)
#pragma unroll
                for (int j = 0; j < 8; j++) acc[i][j] += a[i] * b[j];
        }
    }
#pragma unroll
    for (int i = 0; i < 8; i++) atomicAdd(&s_den[8 * ty + i], dloc[i]);
    __syncthreads();
#pragma unroll
    for (int i = 0; i < 8; i++) {
        int il = 8 * ty + i;
        float inv = 1.f / s_den[il];
        float4 v0 = make_float4(acc[i][0] * inv, acc[i][1] * inv, acc[i][2] * inv, acc[i][3] * inv);
        float4 v1 = make_float4(acc[i][4] * inv, acc[i][5] * inv, acc[i][6] * inv, acc[i][7] * inv);
        float* o = &g_O[((size_t)bh * Nn + i0 + il) * HD + 8 * tx];
        *(float4*)o = v0;
        *(float4*)(o + 4) = v1;
    }
}

// ---------------------------------------------------------------------------
// Kernel 5: output projection  out = concat_heads(O) @ Wp^T + bp
// tile 128x64, 128 threads, 8x8
// ---------------------------------------------------------------------------
__global__ __launch_bounds__(128) void outproj_kernel(const float* __restrict__ Wp,
                                                      const float* __restrict__ bp,
                                                      float* __restrict__ out) {
    __shared__ float As[128][33];
    __shared__ float Bs[64][33];
    int tid = threadIdx.x;
    int tx = tid & 7, ty = tid >> 3;
    int m0 = blockIdx.y * 128, n0 = blockIdx.x * 64;
    float acc[8][8] = {};
    for (int k0 = 0; k0 < Cc; k0 += 32) {
        int h = k0 >> 6;                      // head constant across 32-chunk
#pragma unroll
        for (int l = tid; l < 1024; l += 128) {
            int m = l >> 3, c = (l & 7) * 4;
            int mg = m0 + m;
            int bb = mg >> 11, nl = mg & (Nn - 1);
            int d = (k0 + c) & 63;
            float4 v = *(const float4*)&g_O[(((size_t)(bb * Hh + h)) * Nn + nl) * HD + d];
            As[m][c] = v.x; As[m][c + 1] = v.y; As[m][c + 2] = v.z; As[m][c + 3] = v.w;
        }
#pragma unroll
        for (int l = tid; l < 512; l += 128) {
            int n = l >> 3, c = (l & 7) * 4;
            float4 v = *(const float4*)&Wp[(size_t)(n0 + n) * Cc + k0 + c];
            Bs[n][c] = v.x; Bs[n][c + 1] = v.y; Bs[n][c + 2] = v.z; Bs[n][c + 3] = v.w;
        }
        __syncthreads();
#pragma unroll
        for (int kk = 0; kk < 32; kk++) {
            float a[8], b[8];
#pragma unroll
            for (int i = 0; i < 8; i++) a[i] = As[8 * ty + i][kk];
#pragma unroll
            for (int j = 0; j < 8; j++) b[j] = Bs[8 * tx + j][kk];
#pragma unroll
            for (int i = 0; i < 8; i++)
#pragma unroll
                for (int j = 0; j < 8; j++) acc[i][j] += a[i] * b[j];
        }
        __syncthreads();
    }
#pragma unroll
    for (int i = 0; i < 8; i++) {
        int m = m0 + 8 * ty + i;
#pragma unroll
        for (int j = 0; j < 8; j++) {
            int n = n0 + 8 * tx + j;
            out[(size_t)m * Cc + n] = acc[i][j] + bp[n];
        }
    }
}

// ---------------------------------------------------------------------------
extern "C" void kernel_launch(void* const* d_in, const int* in_sizes, int n_in,
                              void* d_out, int out_size) {
    (void)in_sizes; (void)n_in; (void)out_size;
    const float* q   = (const float*)d_in[0];
    const float* k_v = (const float*)d_in[1];
    const float* Wq  = (const float*)d_in[2];
    const float* Wk  = (const float*)d_in[3];
    const float* Wv  = (const float*)d_in[4];
    const float* Wp  = (const float*)d_in[5];
    const float* bp  = (const float*)d_in[6];
    float* out = (float*)d_out;

    dim3 gproj(Cc / 64, (Bb * Nn) / 128);              // (8, 32)
    proj_kernel<<<gproj, 128>>>(q,   Wq, 0);
    proj_kernel<<<gproj, 128>>>(k_v, Wk, 1);
    proj_kernel<<<gproj, 128>>>(k_v, Wv, 2);

    dim3 gqk(Nn / 64, Nn / 128, BH);                   // (32, 16, 16)
    qk_kernel<<<gqk, 128>>>();

    dim3 gsel(BH * Nn, 2);
    select_kernel<<<gsel, 256>>>();

    dim3 gspv(Nn / 128, BH);                           // (16, 16)
    spv_kernel<<<gspv, 128>>>();

    dim3 gout(Cc / 64, (Bb * Nn) / 128);
    outproj_kernel<<<gout, 128>>>(Wp, bp, out);
}